// round 13
// baseline (speedup 1.0000x reference)
#include <cuda_runtime.h>
#include <cuda_fp16.h>
#include <math.h>
#include <stdint.h>

#define NB 16
#define NT 2048
#define NC 2048
#define NH 256
#define BTOT (NB * NT)   // 32768 rows

// Scratch (device globals: allocation-free per harness rules)
__device__ float g_L[NB * NT * NT];         // 268 MB, L[b][i][j] = k_i . q_j * sqrt(C)
__device__ float g_m[BTOT];                 // per (b,j) column max
__device__ float g_rs[BTOT];                // per (b,j) 1/sum
__device__ float g_pm[NB * 32 * NT];        // partial col-max per 64-row slab
__device__ float g_ps[NB * 32 * NT];        // partial col-sum per 64-row slab
__device__ __half g_Wt[3][2 * NH * NC];     // W*64 transposed, 2-term split
__device__ __half g_Kh[2][BTOT * NH];       // K fp16 2-term split
__device__ __half g_Qh[2][BTOT * NH];       // Q fp16 2-term split
__device__ __half g_Vh[BTOT * NH];          // V fp16 [b*NT+j][h]
__device__ __half g_Vth[NB * NH * NT];      // V^T fp16 [b][h][j]

// ---------------------------------------------------------------------------
__device__ __forceinline__ uint32_t smem_u32(const void* p) {
    uint32_t a;
    asm("{ .reg .u64 t; cvta.to.shared.u64 t, %1; cvt.u32.u64 %0, t; }"
        : "=r"(a) : "l"(p));
    return a;
}
__device__ __forceinline__ uint32_t sw64(uint32_t o) { return o ^ ((o >> 3) & 0x30); }

__device__ __forceinline__ void ldsm_x4(uint32_t& r0, uint32_t& r1, uint32_t& r2,
                                        uint32_t& r3, uint32_t addr) {
    asm volatile("ldmatrix.sync.aligned.m8n8.x4.shared.b16 {%0,%1,%2,%3}, [%4];"
                 : "=r"(r0), "=r"(r1), "=r"(r2), "=r"(r3) : "r"(addr));
}
__device__ __forceinline__ void mma_h(float* d, uint32_t a0, uint32_t a1,
                                      uint32_t a2, uint32_t a3,
                                      uint32_t b0, uint32_t b1) {
    asm volatile(
        "mma.sync.aligned.m16n8k16.row.col.f32.f16.f16.f32 "
        "{%0,%1,%2,%3}, {%4,%5,%6,%7}, {%8,%9}, {%0,%1,%2,%3};"
        : "+f"(d[0]), "+f"(d[1]), "+f"(d[2]), "+f"(d[3])
        : "r"(a0), "r"(a1), "r"(a2), "r"(a3), "r"(b0), "r"(b1));
}
__device__ __forceinline__ void cp_async16(uint32_t dst, const void* src) {
    asm volatile("cp.async.cg.shared.global [%0], [%1], 16;"
                 :: "r"(dst), "l"(src) : "memory");
}
#define CP_COMMIT() asm volatile("cp.async.commit_group;" ::: "memory")
#define CP_WAIT0()  asm volatile("cp.async.wait_group 0;" ::: "memory")

// fp16 split-MMA over one 32-wide K chunk, A tiles register-resident.
// Products: (a0,b0), then (a1,b0) if nprod>=2, then (a0,b1) if nprod>=3.
// Each A/B tile is loaded from smem exactly once per ks.
template <int MI>
__device__ __forceinline__ void mma_terms(uint32_t a0b, uint32_t a1b,
                                          uint32_t b0b, uint32_t b1b, int nprod,
                                          int wm, int wn, int lane, float (*acc)[8][4])
{
#pragma unroll
    for (int ks = 0; ks < 2; ks++) {
        const uint32_t kb = ks * 32;
        const uint32_t a_row = (uint32_t)((wm + (lane & 15)) * 64) + kb + (lane >> 4) * 16;
        const uint32_t b_row = (uint32_t)((wn + (lane & 7) + ((lane >> 4) & 1) * 8) * 64) +
                               kb + ((lane >> 3) & 1) * 16;
        uint32_t A0[MI][4], A1[MI][4];
#pragma unroll
        for (int mi = 0; mi < MI; mi++)
            ldsm_x4(A0[mi][0], A0[mi][1], A0[mi][2], A0[mi][3],
                    a0b + sw64(a_row + (uint32_t)(mi * 16 * 64)));
        if (nprod >= 2) {
#pragma unroll
            for (int mi = 0; mi < MI; mi++)
                ldsm_x4(A1[mi][0], A1[mi][1], A1[mi][2], A1[mi][3],
                        a1b + sw64(a_row + (uint32_t)(mi * 16 * 64)));
        }
#pragma unroll
        for (int nj = 0; nj < 4; nj++) {
            uint32_t b4[4];
            ldsm_x4(b4[0], b4[1], b4[2], b4[3],
                    b0b + sw64(b_row + (uint32_t)(nj * 16 * 64)));
#pragma unroll
            for (int mi = 0; mi < MI; mi++) {
                mma_h(acc[mi][2 * nj],     A0[mi][0], A0[mi][1], A0[mi][2], A0[mi][3], b4[0], b4[1]);
                mma_h(acc[mi][2 * nj + 1], A0[mi][0], A0[mi][1], A0[mi][2], A0[mi][3], b4[2], b4[3]);
            }
            if (nprod >= 2) {
#pragma unroll
                for (int mi = 0; mi < MI; mi++) {
                    mma_h(acc[mi][2 * nj],     A1[mi][0], A1[mi][1], A1[mi][2], A1[mi][3], b4[0], b4[1]);
                    mma_h(acc[mi][2 * nj + 1], A1[mi][0], A1[mi][1], A1[mi][2], A1[mi][3], b4[2], b4[3]);
                }
            }
            if (nprod >= 3) {
                uint32_t c4[4];
                ldsm_x4(c4[0], c4[1], c4[2], c4[3],
                        b1b + sw64(b_row + (uint32_t)(nj * 16 * 64)));
#pragma unroll
                for (int mi = 0; mi < MI; mi++) {
                    mma_h(acc[mi][2 * nj],     A0[mi][0], A0[mi][1], A0[mi][2], A0[mi][3], c4[0], c4[1]);
                    mma_h(acc[mi][2 * nj + 1], A0[mi][0], A0[mi][1], A0[mi][2], A0[mi][3], c4[2], c4[3]);
                }
            }
        }
    }
}

// ---------------------------------------------------------------------------
// Kernel 0: weights: transpose, scale x64 (avoid fp16 subnormals), 2-term split
// ---------------------------------------------------------------------------
__global__ void wprep_kernel(const float* __restrict__ Wk,
                             const float* __restrict__ Wq,
                             const float* __restrict__ Wv)
{
    const float* W = (blockIdx.z == 0) ? Wk : (blockIdx.z == 1) ? Wq : Wv;
    __half* dst = g_Wt[blockIdx.z];
    __shared__ float tile[32][33];
    int k0 = blockIdx.x * 32, n0 = blockIdx.y * 32;
    int tx = threadIdx.x, ty = threadIdx.y;  // (32, 8)
#pragma unroll
    for (int i = 0; i < 32; i += 8)
        tile[ty + i][tx] = W[(size_t)(k0 + ty + i) * NH + n0 + tx];
    __syncthreads();
#pragma unroll
    for (int i = 0; i < 32; i += 8) {
        int n = n0 + ty + i, k = k0 + tx;
        float w = tile[tx][ty + i] * 64.0f;
        __half h1 = __float2half_rn(w);
        __half h2 = __float2half_rn(w - __half2float(h1));
        size_t o = (size_t)n * NC + k;
        dst[o] = h1;
        dst[(size_t)NH * NC + o] = h2;
    }
}

// ---------------------------------------------------------------------------
// Kernel 1: projection.  4 warps (128 thr), CTA tile 128x128, warp tile 64x64,
// 2 CTAs/SM.  blockIdx.x = which*2 + ntile (fastest -> L2 reuse of X).
// K,Q: 3 products -> fp16 split pairs.  V: 1 product -> fp16.
// ---------------------------------------------------------------------------
#define PJ_STG 32768     // A0 8K | A1 8K | B0 8K | B1 8K
#define PJ_SMEM (2 * PJ_STG)

__global__ void __launch_bounds__(128, 2) proj_h_kernel(const float* __restrict__ X)
{
    extern __shared__ char sm[];
    const uint32_t smb = smem_u32(sm);
    const int tid = threadIdx.x, wid = tid >> 5, lane = tid & 31;
    const int wm = (wid >> 1) * 64, wn = (wid & 1) * 64;
    const int which = blockIdx.x >> 1, nt = blockIdx.x & 1;
    const int m0 = blockIdx.y * 128, n0 = nt * 128;
    const __half* Wp = g_Wt[which];
    const int nprod = (which == 2) ? 1 : 3;
    const int ar = tid >> 3, au = tid & 7;   // A loader: 16 rows x 8 f4-slots

    float acc[4][8][4] = {};

    auto load_x = [&](int c, float4* xv) {
        const float* Xp = X + (size_t)m0 * NC + (size_t)c * 32;
#pragma unroll
        for (int it = 0; it < 8; it++)
            xv[it] = *(const float4*)(Xp + (size_t)(ar + it * 16) * NC + au * 4);
    };
    auto store_a = [&](int buf, const float4* xv) {
#pragma unroll
        for (int it = 0; it < 8; it++) {
            __half x1 = __float2half_rn(xv[it].x), y1 = __float2half_rn(xv[it].y);
            __half z1 = __float2half_rn(xv[it].z), w1 = __float2half_rn(xv[it].w);
            uint32_t off = sw64((uint32_t)((ar + it * 16) * 64 + au * 8));
            *(uint2*)(sm + buf * PJ_STG + off) =
                make_uint2((uint32_t)__half_as_ushort(x1) | ((uint32_t)__half_as_ushort(y1) << 16),
                           (uint32_t)__half_as_ushort(z1) | ((uint32_t)__half_as_ushort(w1) << 16));
            if (nprod >= 2) {
                __half x2 = __float2half_rn(xv[it].x - __half2float(x1));
                __half y2 = __float2half_rn(xv[it].y - __half2float(y1));
                __half z2 = __float2half_rn(xv[it].z - __half2float(z1));
                __half w2 = __float2half_rn(xv[it].w - __half2float(w1));
                *(uint2*)(sm + buf * PJ_STG + 8192 + off) =
                    make_uint2((uint32_t)__half_as_ushort(x2) | ((uint32_t)__half_as_ushort(y2) << 16),
                               (uint32_t)__half_as_ushort(z2) | ((uint32_t)__half_as_ushort(w2) << 16));
            }
        }
    };
    auto issue_b = [&](int c, int buf) {
#pragma unroll
        for (int it = 0; it < 8; it++) {
            int idx = tid + it * 128;      // 1024 granules: 2 terms x 128 rows x 4
            int t = idx >> 9, rem = idx & 511;
            int n = rem >> 2, u = rem & 3;
            cp_async16(smb + buf * PJ_STG + 16384 + t * 8192 + sw64((uint32_t)(n * 64 + u * 16)),
                       Wp + (size_t)t * NH * NC + (size_t)(n0 + n) * NC + (size_t)c * 32 + u * 8);
        }
        CP_COMMIT();
    };

    {
        float4 xv[8];
        load_x(0, xv);
        issue_b(0, 0);
        store_a(0, xv);
        CP_WAIT0();
        __syncthreads();
    }

    const int KT = NC / 32;   // 64
    for (int c = 0; c < KT; c++) {
        const int cur = c & 1;
        float4 xv[8];
        if (c + 1 < KT) {
            issue_b(c + 1, cur ^ 1);
            load_x(c + 1, xv);
        }
        mma_terms<4>(smb + cur * PJ_STG, smb + cur * PJ_STG + 8192,
                     smb + cur * PJ_STG + 16384, smb + cur * PJ_STG + 24576,
                     nprod, wm, wn, lane, acc);
        if (c + 1 < KT) {
            store_a(cur ^ 1, xv);
            CP_WAIT0();
        }
        __syncthreads();
    }

    const float inv = 1.0f / 64.0f;   // undo W prescale
    if (which == 2) {
#pragma unroll
        for (int mi = 0; mi < 4; mi++) {
            int m = m0 + wm + mi * 16 + (lane >> 2);
#pragma unroll
            for (int jj = 0; jj < 8; jj++) {
                int n = n0 + wn + jj * 8 + (lane & 3) * 2;
                *(__half2*)(g_Vh + (size_t)m * NH + n) =
                    __halves2half2(__float2half_rn(acc[mi][jj][0] * inv),
                                   __float2half_rn(acc[mi][jj][1] * inv));
                *(__half2*)(g_Vh + (size_t)(m + 8) * NH + n) =
                    __halves2half2(__float2half_rn(acc[mi][jj][2] * inv),
                                   __float2half_rn(acc[mi][jj][3] * inv));
            }
        }
    } else {
        __half* H1 = (which == 0) ? g_Kh[0] : g_Qh[0];
        __half* H2 = (which == 0) ? g_Kh[1] : g_Qh[1];
        auto store2 = [&](int m, int n, float a, float b) {
            __half a1 = __float2half_rn(a), b1 = __float2half_rn(b);
            __half a2 = __float2half_rn(a - __half2float(a1));
            __half b2 = __float2half_rn(b - __half2float(b1));
            *(__half2*)(H1 + (size_t)m * NH + n) = __halves2half2(a1, b1);
            *(__half2*)(H2 + (size_t)m * NH + n) = __halves2half2(a2, b2);
        };
#pragma unroll
        for (int mi = 0; mi < 4; mi++) {
            int m = m0 + wm + mi * 16 + (lane >> 2);
#pragma unroll
            for (int jj = 0; jj < 8; jj++) {
                int n = n0 + wn + jj * 8 + (lane & 3) * 2;
                store2(m, n, acc[mi][jj][0] * inv, acc[mi][jj][1] * inv);
                store2(m + 8, n, acc[mi][jj][2] * inv, acc[mi][jj][3] * inv);
            }
        }
    }
}

// ---------------------------------------------------------------------------
// Kernel 1b: V transpose: g_Vth[b][h][j] = g_Vh[b*NT+j][h]
// ---------------------------------------------------------------------------
__global__ void vtrans_kernel()
{
    __shared__ __half t[32][33];
    int b = blockIdx.z, j0 = blockIdx.x * 32, h0 = blockIdx.y * 32;
    int tx = threadIdx.x, ty = threadIdx.y;   // (32, 8)
    const __half* src = g_Vh + ((size_t)b * NT + j0) * NH + h0;
#pragma unroll
    for (int i = 0; i < 4; i++)
        t[ty + i * 8][tx] = src[(size_t)(ty + i * 8) * NH + tx];
    __syncthreads();
    __half* dst = g_Vth + ((size_t)b * NH + h0) * NT + j0;
#pragma unroll
    for (int i = 0; i < 4; i++)
        dst[(size_t)(ty + i * 8) * NT + tx] = t[tx][ty + i * 8];
}

// ---------------------------------------------------------------------------
// Kernel 2: logits + partial softmax stats.
// L[b][i][j] = sqrt(C) * K[b][i].Q[b][j].  Tile 128 (i) x 128 (j), K=256.
// 4 warps (128 thr), warp tile 64x64, 2 CTAs/SM.
// Each warp-slab (64 i-rows) reduces per-column (max, sum) into g_pm/g_ps.
// ---------------------------------------------------------------------------
#define LG_STG 32768     // A0 8K | A1 8K | B0 8K | B1 8K
#define LG_SMEM (2 * LG_STG)

__global__ void __launch_bounds__(128, 2) logits_h_kernel()
{
    const int bx = blockIdx.x, by = blockIdx.y, b = blockIdx.z;
    if (bx < by) return;                      // all i < j: fully masked, never read
    const int i0 = bx * 128;
    const int j0 = by * 128;
    const size_t rowb = (size_t)b * NT;

    extern __shared__ char sm[];
    const uint32_t smb = smem_u32(sm);
    const int tid = threadIdx.x;
    const int wid = tid >> 5, lane = tid & 31;
    const int wr = wid >> 1, wc = wid & 1;
    const int wm = wr * 64, wn = wc * 64;

    float acc[4][8][4] = {};

    auto issue_a = [&](int c, int buf) {
#pragma unroll
        for (int it = 0; it < 8; it++) {
            int idx = tid + it * 128;      // 1024: 2 terms x 128 rows x 4
            int t = idx >> 9, rem = idx & 511;
            int r = rem >> 2, u = rem & 3;
            cp_async16(smb + buf * LG_STG + t * 8192 + sw64((uint32_t)(r * 64 + u * 16)),
                       g_Kh[t] + (rowb + i0 + r) * NH + (size_t)c * 32 + u * 8);
        }
    };
    auto issue_b = [&](int c, int buf) {
#pragma unroll
        for (int it = 0; it < 8; it++) {
            int idx = tid + it * 128;
            int t = idx >> 9, rem = idx & 511;
            int n = rem >> 2, u = rem & 3;
            cp_async16(smb + buf * LG_STG + 16384 + t * 8192 + sw64((uint32_t)(n * 64 + u * 16)),
                       g_Qh[t] + (rowb + j0 + n) * NH + (size_t)c * 32 + u * 8);
        }
    };

    issue_a(0, 0);
    issue_b(0, 0);
    CP_COMMIT();
    CP_WAIT0();
    __syncthreads();

    const int KT = NH / 32;   // 8
    for (int c = 0; c < KT; c++) {
        const int cur = c & 1;
        if (c + 1 < KT) {
            issue_a(c + 1, cur ^ 1);
            issue_b(c + 1, cur ^ 1);
            CP_COMMIT();
        }
        mma_terms<4>(smb + cur * LG_STG, smb + cur * LG_STG + 8192,
                     smb + cur * LG_STG + 16384, smb + cur * LG_STG + 24576,
                     3, wm, wn, lane, acc);
        if (c + 1 < KT) CP_WAIT0();
        __syncthreads();
    }

    const float scale = 45.25483399593904f;  // sqrt(2048)
    float* Lb = g_L + (size_t)b * NT * NT;
#pragma unroll
    for (int mi = 0; mi < 4; mi++) {
        int m = wm + mi * 16 + (lane >> 2);
#pragma unroll
        for (int jj = 0; jj < 8; jj++) {
            int n = wn + jj * 8 + (lane & 3) * 2;
            int jg = j0 + n;
            {
                int ig = i0 + m;
                float2 v;
                v.x = (ig >= jg) ? acc[mi][jj][0] * scale : -INFINITY;
                v.y = (ig >= jg + 1) ? acc[mi][jj][1] * scale : -INFINITY;
                *(float2*)(Lb + (size_t)ig * NT + jg) = v;
            }
            {
                int ig = i0 + m + 8;
                float2 v;
                v.x = (ig >= jg) ? acc[mi][jj][2] * scale : -INFINITY;
                v.y = (ig >= jg + 1) ? acc[mi][jj][3] * scale : -INFINITY;
                *(float2*)(Lb + (size_t)ig * NT + jg) = v;
            }
        }
    }

    // ---- partial softmax stats: per-column (max, sum) over this warp's 64 rows
    {
        const int bi2 = bx * 2 + wr;
        float* pmrow = g_pm + ((size_t)b * 32 + bi2) * NT;
        float* psrow = g_ps + ((size_t)b * 32 + bi2) * NT;
#pragma unroll
        for (int jj = 0; jj < 8; jj++) {
#pragma unroll
            for (int q = 0; q < 2; q++) {
                int jg = j0 + wn + jj * 8 + (lane & 3) * 2 + q;
                float v[8];
#pragma unroll
                for (int mi = 0; mi < 4; mi++) {
                    int ig = i0 + wm + mi * 16 + (lane >> 2);
                    v[2 * mi]     = (ig >= jg)     ? acc[mi][jj][q] * scale     : -INFINITY;
                    v[2 * mi + 1] = (ig + 8 >= jg) ? acc[mi][jj][q + 2] * scale : -INFINITY;
                }
                float mc = v[0];
#pragma unroll
                for (int k = 1; k < 8; k++) mc = fmaxf(mc, v[k]);
#pragma unroll
                for (int o = 4; o <= 16; o <<= 1)
                    mc = fmaxf(mc, __shfl_xor_sync(0xffffffffu, mc, o));
                float s = 0.f;
#pragma unroll
                for (int k = 0; k < 8; k++)
                    if (v[k] != -INFINITY) s += __expf(v[k] - mc);
#pragma unroll
                for (int o = 4; o <= 16; o <<= 1)
                    s += __shfl_xor_sync(0xffffffffu, s, o);
                if ((lane >> 2) == 0) { pmrow[jg] = mc; psrow[jg] = s; }
            }
        }
    }
}

// ---------------------------------------------------------------------------
// Kernel 3: combine partial stats -> g_m, g_rs.
// Valid slabs for column j: bi2 >= 2*(j>>7) (exactly the blocks that ran).
// ---------------------------------------------------------------------------
__global__ void __launch_bounds__(128) combine_kernel()
{
    const int j = blockIdx.x * 128 + threadIdx.x;
    const int b = blockIdx.y;
    const int k0 = (j >> 7) * 2;
    const float* pm = g_pm + (size_t)b * 32 * NT;
    const float* ps = g_ps + (size_t)b * 32 * NT;
    float m = -INFINITY;
    for (int k = k0; k < 32; k++) m = fmaxf(m, pm[(size_t)k * NT + j]);
    float s = 0.f;
    for (int k = k0; k < 32; k++) {
        float p = pm[(size_t)k * NT + j];
        if (p != -INFINITY) s += ps[(size_t)k * NT + j] * __expf(p - m);
    }
    g_m[b * NT + j] = m;
    g_rs[b * NT + j] = 1.0f / s;
}

// ---------------------------------------------------------------------------
// Kernel 4: av (fp16 MMA).  out[b][i][h] = sum_{j<=i} P[i][j] * V[j][h]
// Tile M=64 (i) x N=256 (h), 2 CTAs/SM, warp tile 32x64, exp fused in loader.
// ---------------------------------------------------------------------------
#define AV_STG 20480     // A 4K | B 16K
#define AV_SMEM (2 * AV_STG)

__global__ void __launch_bounds__(256, 2) av_h_kernel(float* __restrict__ Out)
{
    extern __shared__ char sm[];
    const uint32_t smb = smem_u32(sm);
    const int tid = threadIdx.x;
    const int wid = tid >> 5, lane = tid & 31;
    const int wm = (wid >> 2) * 32, wn = (wid & 3) * 64;
    const int b = blockIdx.y;
    const int i0 = (gridDim.x - 1 - blockIdx.x) * 64;   // big tiles first
    const float* Lb = g_L + (size_t)b * NT * NT;
    const float* mb = g_m + b * NT;
    const float* rb = g_rs + b * NT;
    const __half* Vt = g_Vth + (size_t)b * NH * NT;
    const int ar = tid >> 3, au = tid & 7;

    float acc[2][8][4] = {};

    auto load_p = [&](int c, float4* lv, float4& m4, float4& r4) {
        m4 = *(const float4*)(mb + c * 32 + au * 4);
        r4 = *(const float4*)(rb + c * 32 + au * 4);
#pragma unroll
        for (int it = 0; it < 2; it++)
            lv[it] = *(const float4*)(Lb + (size_t)(i0 + ar + it * 32) * NT +
                                      (size_t)c * 32 + au * 4);
    };
    auto store_p = [&](int buf, const float4* lv, const float4& m4, const float4& r4) {
#pragma unroll
        for (int it = 0; it < 2; it++) {
            __half px = __float2half_rn(__expf(lv[it].x - m4.x) * r4.x);
            __half py = __float2half_rn(__expf(lv[it].y - m4.y) * r4.y);
            __half pz = __float2half_rn(__expf(lv[it].z - m4.z) * r4.z);
            __half pw = __float2half_rn(__expf(lv[it].w - m4.w) * r4.w);
            uint32_t off = sw64((uint32_t)((ar + it * 32) * 64 + au * 8));
            *(uint2*)(sm + buf * AV_STG + off) =
                make_uint2((uint32_t)__half_as_ushort(px) | ((uint32_t)__half_as_ushort(py) << 16),
                           (uint32_t)__half_as_ushort(pz) | ((uint32_t)__half_as_ushort(pw) << 16));
        }
    };
    auto issue_v = [&](int c, int buf) {
#pragma unroll
        for (int it = 0; it < 4; it++) {
            int idx = tid + it * 256;      // 1024 granules: 256 rows x 4
            int n = idx >> 2, u = idx & 3;
            cp_async16(smb + buf * AV_STG + 4096 + sw64((uint32_t)(n * 64 + u * 16)),
                       Vt + (size_t)n * NT + (size_t)c * 32 + u * 8);
        }
        CP_COMMIT();
    };

    const int KT = (i0 + 64) / 32;

    {
        float4 lv[2], m4, r4;
        load_p(0, lv, m4, r4);
        issue_v(0, 0);
        store_p(0, lv, m4, r4);
        CP_WAIT0();
        __syncthreads();
    }

    for (int c = 0; c < KT; c++) {
        const int cur = c & 1;
        float4 lv[2], m4, r4;
        if (c + 1 < KT) {
            issue_v(c + 1, cur ^ 1);
            load_p(c + 1, lv, m4, r4);
        }
        mma_terms<2>(smb + cur * AV_STG, smb + cur * AV_STG,
                     smb + cur * AV_STG + 4096, smb + cur * AV_STG + 4096,
                     1, wm, wn, lane, acc);
        if (c + 1 < KT) {
            store_p(cur ^ 1, lv, m4, r4);
            CP_WAIT0();
        }
        __syncthreads();
    }

    float* Ob = Out + (size_t)b * NT * NH;
#pragma unroll
    for (int mi = 0; mi < 2; mi++) {
        int m = i0 + wm + mi * 16 + (lane >> 2);
#pragma unroll
        for (int jj = 0; jj < 8; jj++) {
            int n = wn + jj * 8 + (lane & 3) * 2;
            *(float2*)(Ob + (size_t)m * NH + n) = make_float2(acc[mi][jj][0], acc[mi][jj][1]);
            *(float2*)(Ob + (size_t)(m + 8) * NH + n) = make_float2(acc[mi][jj][2], acc[mi][jj][3]);
        }
    }
}

// ---------------------------------------------------------------------------
extern "C" void kernel_launch(void* const* d_in, const int* in_sizes, int n_in,
                              void* d_out, int out_size)
{
    const float* X  = (const float*)d_in[0];   // token_embd [16,2048,2048]
    const float* Wk = (const float*)d_in[1];   // [2048,256]
    const float* Wq = (const float*)d_in[2];
    const float* Wv = (const float*)d_in[3];
    float* out = (float*)d_out;                // [16,2048,256] fp32

    cudaFuncSetAttribute(proj_h_kernel,
                         cudaFuncAttributeMaxDynamicSharedMemorySize, PJ_SMEM);
    cudaFuncSetAttribute(logits_h_kernel,
                         cudaFuncAttributeMaxDynamicSharedMemorySize, LG_SMEM);
    cudaFuncSetAttribute(av_h_kernel,
                         cudaFuncAttributeMaxDynamicSharedMemorySize, AV_SMEM);

    wprep_kernel<<<dim3(NC / 32, NH / 32, 3), dim3(32, 8)>>>(Wk, Wq, Wv);

    // x = which*2 + ntile (fastest) -> 6 consecutive blocks share one X tile in L2
    proj_h_kernel<<<dim3(6, BTOT / 128), 128, PJ_SMEM>>>(X);

    vtrans_kernel<<<dim3(NT / 32, NH / 32, NB), dim3(32, 8)>>>();

    logits_h_kernel<<<dim3(NT / 128, NT / 128, NB), 128, LG_SMEM>>>();

    combine_kernel<<<dim3(NT / 128, NB), 128>>>();

    av_h_kernel<<<dim3(NT / 64, NB), 256, AV_SMEM>>>(out);
}

// round 14
// speedup vs baseline: 1.0264x; 1.0264x over previous
#include <cuda_runtime.h>
#include <cuda_fp16.h>
#include <math.h>
#include <stdint.h>

#define NB 16
#define NT 2048
#define NC 2048
#define NH 256
#define BTOT (NB * NT)   // 32768 rows

// Scratch (device globals: allocation-free per harness rules)
__device__ float g_L[NB * NT * NT];         // 268 MB, L[b][i][j] = k_i . q_j * sqrt(C)
__device__ float g_m[BTOT];                 // per (b,j) column max
__device__ float g_rs[BTOT];                // per (b,j) 1/sum
__device__ float g_pm[NB * 32 * NT];        // partial col-max per 64-row slab
__device__ float g_ps[NB * 32 * NT];        // partial col-sum per 64-row slab
__device__ __half g_Wt[3][2 * NH * NC];     // W*64 transposed, 2-term split
__device__ __half g_Kh[2][BTOT * NH];       // K fp16 2-term split
__device__ __half g_Qh[2][BTOT * NH];       // Q fp16 2-term split
__device__ __half g_Vh[BTOT * NH];          // V fp16 [b*NT+j][h]
__device__ __half g_Vth[NB * NH * NT];      // V^T fp16 [b][h][j]

// ---------------------------------------------------------------------------
__device__ __forceinline__ uint32_t smem_u32(const void* p) {
    uint32_t a;
    asm("{ .reg .u64 t; cvta.to.shared.u64 t, %1; cvt.u32.u64 %0, t; }"
        : "=r"(a) : "l"(p));
    return a;
}
__device__ __forceinline__ uint32_t sw64(uint32_t o) { return o ^ ((o >> 3) & 0x30); }

__device__ __forceinline__ void ldsm_x4(uint32_t& r0, uint32_t& r1, uint32_t& r2,
                                        uint32_t& r3, uint32_t addr) {
    asm volatile("ldmatrix.sync.aligned.m8n8.x4.shared.b16 {%0,%1,%2,%3}, [%4];"
                 : "=r"(r0), "=r"(r1), "=r"(r2), "=r"(r3) : "r"(addr));
}
__device__ __forceinline__ void mma_h(float* d, uint32_t a0, uint32_t a1,
                                      uint32_t a2, uint32_t a3,
                                      uint32_t b0, uint32_t b1) {
    asm volatile(
        "mma.sync.aligned.m16n8k16.row.col.f32.f16.f16.f32 "
        "{%0,%1,%2,%3}, {%4,%5,%6,%7}, {%8,%9}, {%0,%1,%2,%3};"
        : "+f"(d[0]), "+f"(d[1]), "+f"(d[2]), "+f"(d[3])
        : "r"(a0), "r"(a1), "r"(a2), "r"(a3), "r"(b0), "r"(b1));
}
__device__ __forceinline__ void cp_async16(uint32_t dst, const void* src) {
    asm volatile("cp.async.cg.shared.global [%0], [%1], 16;"
                 :: "r"(dst), "l"(src) : "memory");
}
#define CP_COMMIT() asm volatile("cp.async.commit_group;" ::: "memory")
#define CP_WAIT0()  asm volatile("cp.async.wait_group 0;" ::: "memory")

// Generic fp16 split-MMA over one 32-wide K chunk (R11 structure: reload A per
// product — keeps live register set small, ptxas schedules without spills).
// Product order: P0=(a0,b0), P1=(a1,b0), P2=(a0,b1); nprod = prefix length.
template <int MI>
__device__ __forceinline__ void mma_terms(uint32_t a0, uint32_t a1,
                                          uint32_t b0, uint32_t b1, int nprod,
                                          int wm, int wn, int lane, float (*acc)[8][4])
{
    const int TAc[3] = {0, 1, 0};
    const int TBc[3] = {0, 0, 1};
#pragma unroll
    for (int ks = 0; ks < 2; ks++) {
        const uint32_t kb = ks * 32;
        const uint32_t a_row = (uint32_t)((wm + (lane & 15)) * 64) + kb + (lane >> 4) * 16;
        const uint32_t b_row = (uint32_t)((wn + (lane & 7) + ((lane >> 4) & 1) * 8) * 64) +
                               kb + ((lane >> 3) & 1) * 16;
#pragma unroll
        for (int p = 0; p < 3; p++) {
            if (p >= nprod) continue;
            const uint32_t ab = TAc[p] ? a1 : a0;
            const uint32_t bb = TBc[p] ? b1 : b0;
            uint32_t af4[MI][4];
#pragma unroll
            for (int mi = 0; mi < MI; mi++)
                ldsm_x4(af4[mi][0], af4[mi][1], af4[mi][2], af4[mi][3],
                        ab + sw64(a_row + (uint32_t)(mi * 16 * 64)));
#pragma unroll
            for (int nj = 0; nj < 4; nj++) {
                uint32_t b4[4];
                ldsm_x4(b4[0], b4[1], b4[2], b4[3],
                        bb + sw64(b_row + (uint32_t)(nj * 16 * 64)));
#pragma unroll
                for (int mi = 0; mi < MI; mi++) {
                    mma_h(acc[mi][2 * nj], af4[mi][0], af4[mi][1], af4[mi][2], af4[mi][3],
                          b4[0], b4[1]);
                    mma_h(acc[mi][2 * nj + 1], af4[mi][0], af4[mi][1], af4[mi][2], af4[mi][3],
                          b4[2], b4[3]);
                }
            }
        }
    }
}

// ---------------------------------------------------------------------------
// Kernel 0: weights: transpose, scale x64 (avoid fp16 subnormals), 2-term split
// ---------------------------------------------------------------------------
__global__ void wprep_kernel(const float* __restrict__ Wk,
                             const float* __restrict__ Wq,
                             const float* __restrict__ Wv)
{
    const float* W = (blockIdx.z == 0) ? Wk : (blockIdx.z == 1) ? Wq : Wv;
    __half* dst = g_Wt[blockIdx.z];
    __shared__ float tile[32][33];
    int k0 = blockIdx.x * 32, n0 = blockIdx.y * 32;
    int tx = threadIdx.x, ty = threadIdx.y;  // (32, 8)
#pragma unroll
    for (int i = 0; i < 32; i += 8)
        tile[ty + i][tx] = W[(size_t)(k0 + ty + i) * NH + n0 + tx];
    __syncthreads();
#pragma unroll
    for (int i = 0; i < 32; i += 8) {
        int n = n0 + ty + i, k = k0 + tx;
        float w = tile[tx][ty + i] * 64.0f;
        __half h1 = __float2half_rn(w);
        __half h2 = __float2half_rn(w - __half2float(h1));
        size_t o = (size_t)n * NC + k;
        dst[o] = h1;
        dst[(size_t)NH * NC + o] = h2;
    }
}

// ---------------------------------------------------------------------------
// Kernel 1: projection.  4 warps (128 thr), CTA tile 128x128, warp tile 64x64,
// 2 CTAs/SM.  blockIdx.x = which*2 + ntile (fastest -> L2 reuse of X).
// K,Q: 3 products -> fp16 split pairs.  V: 1 product -> fp16.
// ---------------------------------------------------------------------------
#define PJ_STG 32768     // A0 8K | A1 8K | B0 8K | B1 8K
#define PJ_SMEM (2 * PJ_STG)

__global__ void __launch_bounds__(128, 2) proj_h_kernel(const float* __restrict__ X)
{
    extern __shared__ char sm[];
    const uint32_t smb = smem_u32(sm);
    const int tid = threadIdx.x, wid = tid >> 5, lane = tid & 31;
    const int wm = (wid >> 1) * 64, wn = (wid & 1) * 64;
    const int which = blockIdx.x >> 1, nt = blockIdx.x & 1;
    const int m0 = blockIdx.y * 128, n0 = nt * 128;
    const __half* Wp = g_Wt[which];
    const int nprod = (which == 2) ? 1 : 3;
    const int ar = tid >> 3, au = tid & 7;   // A loader: 16 rows x 8 f4-slots

    float acc[4][8][4] = {};

    auto load_x = [&](int c, float4* xv) {
        const float* Xp = X + (size_t)m0 * NC + (size_t)c * 32;
#pragma unroll
        for (int it = 0; it < 8; it++)
            xv[it] = *(const float4*)(Xp + (size_t)(ar + it * 16) * NC + au * 4);
    };
    auto store_a = [&](int buf, const float4* xv) {
#pragma unroll
        for (int it = 0; it < 8; it++) {
            __half x1 = __float2half_rn(xv[it].x), y1 = __float2half_rn(xv[it].y);
            __half z1 = __float2half_rn(xv[it].z), w1 = __float2half_rn(xv[it].w);
            uint32_t off = sw64((uint32_t)((ar + it * 16) * 64 + au * 8));
            *(uint2*)(sm + buf * PJ_STG + off) =
                make_uint2((uint32_t)__half_as_ushort(x1) | ((uint32_t)__half_as_ushort(y1) << 16),
                           (uint32_t)__half_as_ushort(z1) | ((uint32_t)__half_as_ushort(w1) << 16));
            if (nprod >= 2) {
                __half x2 = __float2half_rn(xv[it].x - __half2float(x1));
                __half y2 = __float2half_rn(xv[it].y - __half2float(y1));
                __half z2 = __float2half_rn(xv[it].z - __half2float(z1));
                __half w2 = __float2half_rn(xv[it].w - __half2float(w1));
                *(uint2*)(sm + buf * PJ_STG + 8192 + off) =
                    make_uint2((uint32_t)__half_as_ushort(x2) | ((uint32_t)__half_as_ushort(y2) << 16),
                               (uint32_t)__half_as_ushort(z2) | ((uint32_t)__half_as_ushort(w2) << 16));
            }
        }
    };
    auto issue_b = [&](int c, int buf) {
#pragma unroll
        for (int it = 0; it < 8; it++) {
            int idx = tid + it * 128;      // 1024 granules: 2 terms x 128 rows x 4
            int t = idx >> 9, rem = idx & 511;
            int n = rem >> 2, u = rem & 3;
            cp_async16(smb + buf * PJ_STG + 16384 + t * 8192 + sw64((uint32_t)(n * 64 + u * 16)),
                       Wp + (size_t)t * NH * NC + (size_t)(n0 + n) * NC + (size_t)c * 32 + u * 8);
        }
        CP_COMMIT();
    };

    {
        float4 xv[8];
        load_x(0, xv);
        issue_b(0, 0);
        store_a(0, xv);
        CP_WAIT0();
        __syncthreads();
    }

    const int KT = NC / 32;   // 64
    for (int c = 0; c < KT; c++) {
        const int cur = c & 1;
        float4 xv[8];
        if (c + 1 < KT) {
            issue_b(c + 1, cur ^ 1);
            load_x(c + 1, xv);
        }
        mma_terms<4>(smb + cur * PJ_STG, smb + cur * PJ_STG + 8192,
                     smb + cur * PJ_STG + 16384, smb + cur * PJ_STG + 24576,
                     nprod, wm, wn, lane, acc);
        if (c + 1 < KT) {
            store_a(cur ^ 1, xv);
            CP_WAIT0();
        }
        __syncthreads();
    }

    const float inv = 1.0f / 64.0f;   // undo W prescale
    if (which == 2) {
#pragma unroll
        for (int mi = 0; mi < 4; mi++) {
            int m = m0 + wm + mi * 16 + (lane >> 2);
#pragma unroll
            for (int jj = 0; jj < 8; jj++) {
                int n = n0 + wn + jj * 8 + (lane & 3) * 2;
                *(__half2*)(g_Vh + (size_t)m * NH + n) =
                    __halves2half2(__float2half_rn(acc[mi][jj][0] * inv),
                                   __float2half_rn(acc[mi][jj][1] * inv));
                *(__half2*)(g_Vh + (size_t)(m + 8) * NH + n) =
                    __halves2half2(__float2half_rn(acc[mi][jj][2] * inv),
                                   __float2half_rn(acc[mi][jj][3] * inv));
            }
        }
    } else {
        __half* H1 = (which == 0) ? g_Kh[0] : g_Qh[0];
        __half* H2 = (which == 0) ? g_Kh[1] : g_Qh[1];
        auto store2 = [&](int m, int n, float a, float b) {
            __half a1 = __float2half_rn(a), b1 = __float2half_rn(b);
            __half a2 = __float2half_rn(a - __half2float(a1));
            __half b2 = __float2half_rn(b - __half2float(b1));
            *(__half2*)(H1 + (size_t)m * NH + n) = __halves2half2(a1, b1);
            *(__half2*)(H2 + (size_t)m * NH + n) = __halves2half2(a2, b2);
        };
#pragma unroll
        for (int mi = 0; mi < 4; mi++) {
            int m = m0 + wm + mi * 16 + (lane >> 2);
#pragma unroll
            for (int jj = 0; jj < 8; jj++) {
                int n = n0 + wn + jj * 8 + (lane & 3) * 2;
                store2(m, n, acc[mi][jj][0] * inv, acc[mi][jj][1] * inv);
                store2(m + 8, n, acc[mi][jj][2] * inv, acc[mi][jj][3] * inv);
            }
        }
    }
}

// ---------------------------------------------------------------------------
// Kernel 1b: V transpose: g_Vth[b][h][j] = g_Vh[b*NT+j][h]
// ---------------------------------------------------------------------------
__global__ void vtrans_kernel()
{
    __shared__ __half t[32][33];
    int b = blockIdx.z, j0 = blockIdx.x * 32, h0 = blockIdx.y * 32;
    int tx = threadIdx.x, ty = threadIdx.y;   // (32, 8)
    const __half* src = g_Vh + ((size_t)b * NT + j0) * NH + h0;
#pragma unroll
    for (int i = 0; i < 4; i++)
        t[ty + i * 8][tx] = src[(size_t)(ty + i * 8) * NH + tx];
    __syncthreads();
    __half* dst = g_Vth + ((size_t)b * NH + h0) * NT + j0;
#pragma unroll
    for (int i = 0; i < 4; i++)
        dst[(size_t)(ty + i * 8) * NT + tx] = t[tx][ty + i * 8];
}

// ---------------------------------------------------------------------------
// Kernel 2: logits + partial softmax stats.
// L[b][i][j] = sqrt(C) * K[b][i].Q[b][j].  Tile 128 (i) x 128 (j), K=256.
// 4 warps (128 thr), warp tile 64x64, 2 CTAs/SM.
// Each warp-slab (64 i-rows) reduces per-column (max, sum) into g_pm/g_ps.
// ---------------------------------------------------------------------------
#define LG_STG 32768     // A0 8K | A1 8K | B0 8K | B1 8K
#define LG_SMEM (2 * LG_STG)

__global__ void __launch_bounds__(128, 2) logits_h_kernel()
{
    const int bx = blockIdx.x, by = blockIdx.y, b = blockIdx.z;
    if (bx < by) return;                      // all i < j: fully masked, never read
    const int i0 = bx * 128;
    const int j0 = by * 128;
    const size_t rowb = (size_t)b * NT;

    extern __shared__ char sm[];
    const uint32_t smb = smem_u32(sm);
    const int tid = threadIdx.x;
    const int wid = tid >> 5, lane = tid & 31;
    const int wr = wid >> 1, wc = wid & 1;
    const int wm = wr * 64, wn = wc * 64;

    float acc[4][8][4] = {};

    auto issue_a = [&](int c, int buf) {
#pragma unroll
        for (int it = 0; it < 8; it++) {
            int idx = tid + it * 128;      // 1024: 2 terms x 128 rows x 4
            int t = idx >> 9, rem = idx & 511;
            int r = rem >> 2, u = rem & 3;
            cp_async16(smb + buf * LG_STG + t * 8192 + sw64((uint32_t)(r * 64 + u * 16)),
                       g_Kh[t] + (rowb + i0 + r) * NH + (size_t)c * 32 + u * 8);
        }
    };
    auto issue_b = [&](int c, int buf) {
#pragma unroll
        for (int it = 0; it < 8; it++) {
            int idx = tid + it * 128;
            int t = idx >> 9, rem = idx & 511;
            int n = rem >> 2, u = rem & 3;
            cp_async16(smb + buf * LG_STG + 16384 + t * 8192 + sw64((uint32_t)(n * 64 + u * 16)),
                       g_Qh[t] + (rowb + j0 + n) * NH + (size_t)c * 32 + u * 8);
        }
    };

    issue_a(0, 0);
    issue_b(0, 0);
    CP_COMMIT();
    CP_WAIT0();
    __syncthreads();

    const int KT = NH / 32;   // 8
    for (int c = 0; c < KT; c++) {
        const int cur = c & 1;
        if (c + 1 < KT) {
            issue_a(c + 1, cur ^ 1);
            issue_b(c + 1, cur ^ 1);
            CP_COMMIT();
        }
        mma_terms<4>(smb + cur * LG_STG, smb + cur * LG_STG + 8192,
                     smb + cur * LG_STG + 16384, smb + cur * LG_STG + 24576,
                     3, wm, wn, lane, acc);
        if (c + 1 < KT) CP_WAIT0();
        __syncthreads();
    }

    const float scale = 45.25483399593904f;  // sqrt(2048)
    float* Lb = g_L + (size_t)b * NT * NT;
#pragma unroll
    for (int mi = 0; mi < 4; mi++) {
        int m = wm + mi * 16 + (lane >> 2);
#pragma unroll
        for (int jj = 0; jj < 8; jj++) {
            int n = wn + jj * 8 + (lane & 3) * 2;
            int jg = j0 + n;
            {
                int ig = i0 + m;
                float2 v;
                v.x = (ig >= jg) ? acc[mi][jj][0] * scale : -INFINITY;
                v.y = (ig >= jg + 1) ? acc[mi][jj][1] * scale : -INFINITY;
                *(float2*)(Lb + (size_t)ig * NT + jg) = v;
            }
            {
                int ig = i0 + m + 8;
                float2 v;
                v.x = (ig >= jg) ? acc[mi][jj][2] * scale : -INFINITY;
                v.y = (ig >= jg + 1) ? acc[mi][jj][3] * scale : -INFINITY;
                *(float2*)(Lb + (size_t)ig * NT + jg) = v;
            }
        }
    }

    // ---- partial softmax stats: per-column (max, sum) over this warp's 64 rows
    {
        const int bi2 = bx * 2 + wr;
        float* pmrow = g_pm + ((size_t)b * 32 + bi2) * NT;
        float* psrow = g_ps + ((size_t)b * 32 + bi2) * NT;
#pragma unroll
        for (int jj = 0; jj < 8; jj++) {
#pragma unroll
            for (int q = 0; q < 2; q++) {
                int jg = j0 + wn + jj * 8 + (lane & 3) * 2 + q;
                float v[8];
#pragma unroll
                for (int mi = 0; mi < 4; mi++) {
                    int ig = i0 + wm + mi * 16 + (lane >> 2);
                    v[2 * mi]     = (ig >= jg)     ? acc[mi][jj][q] * scale     : -INFINITY;
                    v[2 * mi + 1] = (ig + 8 >= jg) ? acc[mi][jj][q + 2] * scale : -INFINITY;
                }
                float mc = v[0];
#pragma unroll
                for (int k = 1; k < 8; k++) mc = fmaxf(mc, v[k]);
#pragma unroll
                for (int o = 4; o <= 16; o <<= 1)
                    mc = fmaxf(mc, __shfl_xor_sync(0xffffffffu, mc, o));
                float s = 0.f;
#pragma unroll
                for (int k = 0; k < 8; k++)
                    if (v[k] != -INFINITY) s += __expf(v[k] - mc);
#pragma unroll
                for (int o = 4; o <= 16; o <<= 1)
                    s += __shfl_xor_sync(0xffffffffu, s, o);
                if ((lane >> 2) == 0) { pmrow[jg] = mc; psrow[jg] = s; }
            }
        }
    }
}

// ---------------------------------------------------------------------------
// Kernel 3: combine partial stats -> g_m, g_rs.
// Valid slabs for column j: bi2 >= 2*(j>>7) (exactly the blocks that ran).
// ---------------------------------------------------------------------------
__global__ void __launch_bounds__(128) combine_kernel()
{
    const int j = blockIdx.x * 128 + threadIdx.x;
    const int b = blockIdx.y;
    const int k0 = (j >> 7) * 2;
    const float* pm = g_pm + (size_t)b * 32 * NT;
    const float* ps = g_ps + (size_t)b * 32 * NT;
    float m = -INFINITY;
    for (int k = k0; k < 32; k++) m = fmaxf(m, pm[(size_t)k * NT + j]);
    float s = 0.f;
    for (int k = k0; k < 32; k++) {
        float p = pm[(size_t)k * NT + j];
        if (p != -INFINITY) s += ps[(size_t)k * NT + j] * __expf(p - m);
    }
    g_m[b * NT + j] = m;
    g_rs[b * NT + j] = 1.0f / s;
}

// ---------------------------------------------------------------------------
// Kernel 4: av (fp16 MMA).  out[b][i][h] = sum_{j<=i} P[i][j] * V[j][h]
// Tile M=64 (i) x N=256 (h), 2 CTAs/SM, warp tile 32x64, exp fused in loader.
// ---------------------------------------------------------------------------
#define AV_STG 20480     // A 4K | B 16K
#define AV_SMEM (2 * AV_STG)

__global__ void __launch_bounds__(256, 2) av_h_kernel(float* __restrict__ Out)
{
    extern __shared__ char sm[];
    const uint32_t smb = smem_u32(sm);
    const int tid = threadIdx.x;
    const int wid = tid >> 5, lane = tid & 31;
    const int wm = (wid >> 2) * 32, wn = (wid & 3) * 64;
    const int b = blockIdx.y;
    const int i0 = (gridDim.x - 1 - blockIdx.x) * 64;   // big tiles first
    const float* Lb = g_L + (size_t)b * NT * NT;
    const float* mb = g_m + b * NT;
    const float* rb = g_rs + b * NT;
    const __half* Vt = g_Vth + (size_t)b * NH * NT;
    const int ar = tid >> 3, au = tid & 7;

    float acc[2][8][4] = {};

    auto load_p = [&](int c, float4* lv, float4& m4, float4& r4) {
        m4 = *(const float4*)(mb + c * 32 + au * 4);
        r4 = *(const float4*)(rb + c * 32 + au * 4);
#pragma unroll
        for (int it = 0; it < 2; it++)
            lv[it] = *(const float4*)(Lb + (size_t)(i0 + ar + it * 32) * NT +
                                      (size_t)c * 32 + au * 4);
    };
    auto store_p = [&](int buf, const float4* lv, const float4& m4, const float4& r4) {
#pragma unroll
        for (int it = 0; it < 2; it++) {
            __half px = __float2half_rn(__expf(lv[it].x - m4.x) * r4.x);
            __half py = __float2half_rn(__expf(lv[it].y - m4.y) * r4.y);
            __half pz = __float2half_rn(__expf(lv[it].z - m4.z) * r4.z);
            __half pw = __float2half_rn(__expf(lv[it].w - m4.w) * r4.w);
            uint32_t off = sw64((uint32_t)((ar + it * 32) * 64 + au * 8));
            *(uint2*)(sm + buf * AV_STG + off) =
                make_uint2((uint32_t)__half_as_ushort(px) | ((uint32_t)__half_as_ushort(py) << 16),
                           (uint32_t)__half_as_ushort(pz) | ((uint32_t)__half_as_ushort(pw) << 16));
        }
    };
    auto issue_v = [&](int c, int buf) {
#pragma unroll
        for (int it = 0; it < 4; it++) {
            int idx = tid + it * 256;      // 1024 granules: 256 rows x 4
            int n = idx >> 2, u = idx & 3;
            cp_async16(smb + buf * AV_STG + 4096 + sw64((uint32_t)(n * 64 + u * 16)),
                       Vt + (size_t)n * NT + (size_t)c * 32 + u * 8);
        }
        CP_COMMIT();
    };

    const int KT = (i0 + 64) / 32;

    {
        float4 lv[2], m4, r4;
        load_p(0, lv, m4, r4);
        issue_v(0, 0);
        store_p(0, lv, m4, r4);
        CP_WAIT0();
        __syncthreads();
    }

    for (int c = 0; c < KT; c++) {
        const int cur = c & 1;
        float4 lv[2], m4, r4;
        if (c + 1 < KT) {
            issue_v(c + 1, cur ^ 1);
            load_p(c + 1, lv, m4, r4);
        }
        mma_terms<2>(smb + cur * AV_STG, smb + cur * AV_STG,
                     smb + cur * AV_STG + 4096, smb + cur * AV_STG + 4096,
                     1, wm, wn, lane, acc);
        if (c + 1 < KT) {
            store_p(cur ^ 1, lv, m4, r4);
            CP_WAIT0();
        }
        __syncthreads();
    }

    float* Ob = Out + (size_t)b * NT * NH;
#pragma unroll
    for (int mi = 0; mi < 2; mi++) {
        int m = i0 + wm + mi * 16 + (lane >> 2);
#pragma unroll
        for (int jj = 0; jj < 8; jj++) {
            int n = wn + jj * 8 + (lane & 3) * 2;
            *(float2*)(Ob + (size_t)m * NH + n) = make_float2(acc[mi][jj][0], acc[mi][jj][1]);
            *(float2*)(Ob + (size_t)(m + 8) * NH + n) = make_float2(acc[mi][jj][2], acc[mi][jj][3]);
        }
    }
}

// ---------------------------------------------------------------------------
extern "C" void kernel_launch(void* const* d_in, const int* in_sizes, int n_in,
                              void* d_out, int out_size)
{
    const float* X  = (const float*)d_in[0];   // token_embd [16,2048,2048]
    const float* Wk = (const float*)d_in[1];   // [2048,256]
    const float* Wq = (const float*)d_in[2];
    const float* Wv = (const float*)d_in[3];
    float* out = (float*)d_out;                // [16,2048,256] fp32

    cudaFuncSetAttribute(proj_h_kernel,
                         cudaFuncAttributeMaxDynamicSharedMemorySize, PJ_SMEM);
    cudaFuncSetAttribute(logits_h_kernel,
                         cudaFuncAttributeMaxDynamicSharedMemorySize, LG_SMEM);
    cudaFuncSetAttribute(av_h_kernel,
                         cudaFuncAttributeMaxDynamicSharedMemorySize, AV_SMEM);

    wprep_kernel<<<dim3(NC / 32, NH / 32, 3), dim3(32, 8)>>>(Wk, Wq, Wv);

    // x = which*2 + ntile (fastest) -> 6 consecutive blocks share one X tile in L2
    proj_h_kernel<<<dim3(6, BTOT / 128), 128, PJ_SMEM>>>(X);

    vtrans_kernel<<<dim3(NT / 32, NH / 32, NB), dim3(32, 8)>>>();

    logits_h_kernel<<<dim3(NT / 128, NT / 128, NB), 128, LG_SMEM>>>();

    combine_kernel<<<dim3(NT / 128, NB), 128>>>();

    av_h_kernel<<<dim3(NT / 64, NB), 256, AV_SMEM>>>(out);
}

// round 15
// speedup vs baseline: 1.1118x; 1.0832x over previous
#include <cuda_runtime.h>
#include <cuda_fp16.h>
#include <math.h>
#include <stdint.h>

#define NB 16
#define NT 2048
#define NC 2048
#define NH 256
#define BTOT (NB * NT)   // 32768 rows

// Scratch (device globals: allocation-free per harness rules)
__device__ float g_L[NB * NT * NT];         // 268 MB, L[b][i][j] = k_i . q_j * sqrt(C)
__device__ float g_m[BTOT];                 // per (b,j) column max
__device__ float g_rs[BTOT];                // per (b,j) 1/sum
__device__ float g_pm[NB * 32 * NT];        // partial col-max per 64-row slab
__device__ float g_ps[NB * 32 * NT];        // partial col-sum per 64-row slab
__device__ __half g_Xh[2][(size_t)BTOT * NC];   // X fp16 2-term split (268 MB)
__device__ __half g_Wt[3][2 * NH * NC];     // W*64 transposed, 2-term split
__device__ __half g_Kh[2][BTOT * NH];       // K fp16 2-term split
__device__ __half g_Qh[2][BTOT * NH];       // Q fp16 2-term split
__device__ __half g_Vh[BTOT * NH];          // V fp16 [b*NT+j][h]
__device__ __half g_Vth[NB * NH * NT];      // V^T fp16 [b][h][j]

// ---------------------------------------------------------------------------
__device__ __forceinline__ uint32_t smem_u32(const void* p) {
    uint32_t a;
    asm("{ .reg .u64 t; cvta.to.shared.u64 t, %1; cvt.u32.u64 %0, t; }"
        : "=r"(a) : "l"(p));
    return a;
}
__device__ __forceinline__ uint32_t sw64(uint32_t o) { return o ^ ((o >> 3) & 0x30); }

__device__ __forceinline__ void ldsm_x4(uint32_t& r0, uint32_t& r1, uint32_t& r2,
                                        uint32_t& r3, uint32_t addr) {
    asm volatile("ldmatrix.sync.aligned.m8n8.x4.shared.b16 {%0,%1,%2,%3}, [%4];"
                 : "=r"(r0), "=r"(r1), "=r"(r2), "=r"(r3) : "r"(addr));
}
__device__ __forceinline__ void mma_h(float* d, uint32_t a0, uint32_t a1,
                                      uint32_t a2, uint32_t a3,
                                      uint32_t b0, uint32_t b1) {
    asm volatile(
        "mma.sync.aligned.m16n8k16.row.col.f32.f16.f16.f32 "
        "{%0,%1,%2,%3}, {%4,%5,%6,%7}, {%8,%9}, {%0,%1,%2,%3};"
        : "+f"(d[0]), "+f"(d[1]), "+f"(d[2]), "+f"(d[3])
        : "r"(a0), "r"(a1), "r"(a2), "r"(a3), "r"(b0), "r"(b1));
}
__device__ __forceinline__ void cp_async16(uint32_t dst, const void* src) {
    asm volatile("cp.async.cg.shared.global [%0], [%1], 16;"
                 :: "r"(dst), "l"(src) : "memory");
}
#define CP_COMMIT() asm volatile("cp.async.commit_group;" ::: "memory")
#define CP_WAIT0()  asm volatile("cp.async.wait_group 0;" ::: "memory")
#define CP_WAIT1()  asm volatile("cp.async.wait_group 1;" ::: "memory")

// Generic fp16 split-MMA over one 32-wide K chunk (R11 structure: reload A per
// product — keeps live register set small, ptxas schedules without spills).
// Product order: P0=(a0,b0), P1=(a1,b0), P2=(a0,b1); nprod = prefix length.
template <int MI>
__device__ __forceinline__ void mma_terms(uint32_t a0, uint32_t a1,
                                          uint32_t b0, uint32_t b1, int nprod,
                                          int wm, int wn, int lane, float (*acc)[8][4])
{
    const int TAc[3] = {0, 1, 0};
    const int TBc[3] = {0, 0, 1};
#pragma unroll
    for (int ks = 0; ks < 2; ks++) {
        const uint32_t kb = ks * 32;
        const uint32_t a_row = (uint32_t)((wm + (lane & 15)) * 64) + kb + (lane >> 4) * 16;
        const uint32_t b_row = (uint32_t)((wn + (lane & 7) + ((lane >> 4) & 1) * 8) * 64) +
                               kb + ((lane >> 3) & 1) * 16;
#pragma unroll
        for (int p = 0; p < 3; p++) {
            if (p >= nprod) continue;
            const uint32_t ab = TAc[p] ? a1 : a0;
            const uint32_t bb = TBc[p] ? b1 : b0;
            uint32_t af4[MI][4];
#pragma unroll
            for (int mi = 0; mi < MI; mi++)
                ldsm_x4(af4[mi][0], af4[mi][1], af4[mi][2], af4[mi][3],
                        ab + sw64(a_row + (uint32_t)(mi * 16 * 64)));
#pragma unroll
            for (int nj = 0; nj < 4; nj++) {
                uint32_t b4[4];
                ldsm_x4(b4[0], b4[1], b4[2], b4[3],
                        bb + sw64(b_row + (uint32_t)(nj * 16 * 64)));
#pragma unroll
                for (int mi = 0; mi < MI; mi++) {
                    mma_h(acc[mi][2 * nj], af4[mi][0], af4[mi][1], af4[mi][2], af4[mi][3],
                          b4[0], b4[1]);
                    mma_h(acc[mi][2 * nj + 1], af4[mi][0], af4[mi][1], af4[mi][2], af4[mi][3],
                          b4[2], b4[3]);
                }
            }
        }
    }
}

// ---------------------------------------------------------------------------
// Kernel 0a: split X once into fp16 2-term globals
// ---------------------------------------------------------------------------
__global__ void xsplit_kernel(const float* __restrict__ X)
{
    const size_t n4 = (size_t)BTOT * NC / 4;
    const size_t stride = (size_t)gridDim.x * blockDim.x;
    uint2* o1 = (uint2*)g_Xh[0];
    uint2* o2 = (uint2*)g_Xh[1];
    for (size_t i = (size_t)blockIdx.x * blockDim.x + threadIdx.x; i < n4; i += stride) {
        float4 v = ((const float4*)X)[i];
        __half x1 = __float2half_rn(v.x), y1 = __float2half_rn(v.y);
        __half z1 = __float2half_rn(v.z), w1 = __float2half_rn(v.w);
        __half x2 = __float2half_rn(v.x - __half2float(x1));
        __half y2 = __float2half_rn(v.y - __half2float(y1));
        __half z2 = __float2half_rn(v.z - __half2float(z1));
        __half w2 = __float2half_rn(v.w - __half2float(w1));
        o1[i] = make_uint2((uint32_t)__half_as_ushort(x1) | ((uint32_t)__half_as_ushort(y1) << 16),
                           (uint32_t)__half_as_ushort(z1) | ((uint32_t)__half_as_ushort(w1) << 16));
        o2[i] = make_uint2((uint32_t)__half_as_ushort(x2) | ((uint32_t)__half_as_ushort(y2) << 16),
                           (uint32_t)__half_as_ushort(z2) | ((uint32_t)__half_as_ushort(w2) << 16));
    }
}

// ---------------------------------------------------------------------------
// Kernel 0b: weights: transpose, scale x64 (avoid fp16 subnormals), 2-term split
// ---------------------------------------------------------------------------
__global__ void wprep_kernel(const float* __restrict__ Wk,
                             const float* __restrict__ Wq,
                             const float* __restrict__ Wv)
{
    const float* W = (blockIdx.z == 0) ? Wk : (blockIdx.z == 1) ? Wq : Wv;
    __half* dst = g_Wt[blockIdx.z];
    __shared__ float tile[32][33];
    int k0 = blockIdx.x * 32, n0 = blockIdx.y * 32;
    int tx = threadIdx.x, ty = threadIdx.y;  // (32, 8)
#pragma unroll
    for (int i = 0; i < 32; i += 8)
        tile[ty + i][tx] = W[(size_t)(k0 + ty + i) * NH + n0 + tx];
    __syncthreads();
#pragma unroll
    for (int i = 0; i < 32; i += 8) {
        int n = n0 + ty + i, k = k0 + tx;
        float w = tile[tx][ty + i] * 64.0f;
        __half h1 = __float2half_rn(w);
        __half h2 = __float2half_rn(w - __half2float(h1));
        size_t o = (size_t)n * NC + k;
        dst[o] = h1;
        dst[(size_t)NH * NC + o] = h2;
    }
}

// ---------------------------------------------------------------------------
// Kernel 1: projection.  4 warps (128 thr), CTA tile 128x128, warp tile 64x64,
// 2 CTAs/SM, 3-stage all-cp.async pipeline (A from pre-split g_Xh).
// blockIdx.x = which*2 + ntile (fastest -> L2 reuse of X).
// K,Q: 3 products -> fp16 split pairs.  V: 1 product -> fp16.
// ---------------------------------------------------------------------------
#define PJ_STG 32768     // A0 8K | A1 8K | B0 8K | B1 8K
#define PJ_SMEM (3 * PJ_STG)

__global__ void __launch_bounds__(128, 2) proj_h_kernel()
{
    extern __shared__ char sm[];
    const uint32_t smb = smem_u32(sm);
    const int tid = threadIdx.x, wid = tid >> 5, lane = tid & 31;
    const int wm = (wid >> 1) * 64, wn = (wid & 1) * 64;
    const int which = blockIdx.x >> 1, nt = blockIdx.x & 1;
    const int m0 = blockIdx.y * 128, n0 = nt * 128;
    const __half* Wp = g_Wt[which];
    const int nprod = (which == 2) ? 1 : 3;
    const int nterm = (nprod >= 2) ? 2 : 1;

    float acc[4][8][4] = {};

    auto issue = [&](int c, int buf) {
        const uint32_t base = smb + buf * PJ_STG;
        // A term 0 (always): 128 rows x 4 granules = 512
#pragma unroll
        for (int it = 0; it < 4; it++) {
            int idx = tid + it * 128;
            int r = idx >> 2, u = idx & 3;
            cp_async16(base + sw64((uint32_t)(r * 64 + u * 16)),
                       g_Xh[0] + (size_t)(m0 + r) * NC + (size_t)c * 32 + u * 8);
        }
        // B term 0 (always)
#pragma unroll
        for (int it = 0; it < 4; it++) {
            int idx = tid + it * 128;
            int n = idx >> 2, u = idx & 3;
            cp_async16(base + 16384 + sw64((uint32_t)(n * 64 + u * 16)),
                       Wp + (size_t)(n0 + n) * NC + (size_t)c * 32 + u * 8);
        }
        if (nterm == 2) {
#pragma unroll
            for (int it = 0; it < 4; it++) {
                int idx = tid + it * 128;
                int r = idx >> 2, u = idx & 3;
                cp_async16(base + 8192 + sw64((uint32_t)(r * 64 + u * 16)),
                           g_Xh[1] + (size_t)(m0 + r) * NC + (size_t)c * 32 + u * 8);
            }
#pragma unroll
            for (int it = 0; it < 4; it++) {
                int idx = tid + it * 128;
                int n = idx >> 2, u = idx & 3;
                cp_async16(base + 24576 + sw64((uint32_t)(n * 64 + u * 16)),
                           Wp + (size_t)NH * NC + (size_t)(n0 + n) * NC + (size_t)c * 32 + u * 8);
            }
        }
        CP_COMMIT();
    };

    const int KT = NC / 32;   // 64
    issue(0, 0);
    issue(1, 1);
    for (int c = 0; c < KT; c++) {
        const int cur = c % 3;
        CP_WAIT1();
        __syncthreads();
        if (c + 2 < KT) issue(c + 2, (c + 2) % 3);
        const uint32_t base = smb + cur * PJ_STG;
        mma_terms<4>(base, base + 8192, base + 16384, base + 24576,
                     nprod, wm, wn, lane, acc);
    }

    const float inv = 1.0f / 64.0f;   // undo W prescale
    if (which == 2) {
#pragma unroll
        for (int mi = 0; mi < 4; mi++) {
            int m = m0 + wm + mi * 16 + (lane >> 2);
#pragma unroll
            for (int jj = 0; jj < 8; jj++) {
                int n = n0 + wn + jj * 8 + (lane & 3) * 2;
                *(__half2*)(g_Vh + (size_t)m * NH + n) =
                    __halves2half2(__float2half_rn(acc[mi][jj][0] * inv),
                                   __float2half_rn(acc[mi][jj][1] * inv));
                *(__half2*)(g_Vh + (size_t)(m + 8) * NH + n) =
                    __halves2half2(__float2half_rn(acc[mi][jj][2] * inv),
                                   __float2half_rn(acc[mi][jj][3] * inv));
            }
        }
    } else {
        __half* H1 = (which == 0) ? g_Kh[0] : g_Qh[0];
        __half* H2 = (which == 0) ? g_Kh[1] : g_Qh[1];
        auto store2 = [&](int m, int n, float a, float b) {
            __half a1 = __float2half_rn(a), b1 = __float2half_rn(b);
            __half a2 = __float2half_rn(a - __half2float(a1));
            __half b2 = __float2half_rn(b - __half2float(b1));
            *(__half2*)(H1 + (size_t)m * NH + n) = __halves2half2(a1, b1);
            *(__half2*)(H2 + (size_t)m * NH + n) = __halves2half2(a2, b2);
        };
#pragma unroll
        for (int mi = 0; mi < 4; mi++) {
            int m = m0 + wm + mi * 16 + (lane >> 2);
#pragma unroll
            for (int jj = 0; jj < 8; jj++) {
                int n = n0 + wn + jj * 8 + (lane & 3) * 2;
                store2(m, n, acc[mi][jj][0] * inv, acc[mi][jj][1] * inv);
                store2(m + 8, n, acc[mi][jj][2] * inv, acc[mi][jj][3] * inv);
            }
        }
    }
}

// ---------------------------------------------------------------------------
// Kernel 1b: V transpose: g_Vth[b][h][j] = g_Vh[b*NT+j][h]
// ---------------------------------------------------------------------------
__global__ void vtrans_kernel()
{
    __shared__ __half t[32][33];
    int b = blockIdx.z, j0 = blockIdx.x * 32, h0 = blockIdx.y * 32;
    int tx = threadIdx.x, ty = threadIdx.y;   // (32, 8)
    const __half* src = g_Vh + ((size_t)b * NT + j0) * NH + h0;
#pragma unroll
    for (int i = 0; i < 4; i++)
        t[ty + i * 8][tx] = src[(size_t)(ty + i * 8) * NH + tx];
    __syncthreads();
    __half* dst = g_Vth + ((size_t)b * NH + h0) * NT + j0;
#pragma unroll
    for (int i = 0; i < 4; i++)
        dst[(size_t)(ty + i * 8) * NT + tx] = t[tx][ty + i * 8];
}

// ---------------------------------------------------------------------------
// Kernel 2: logits + partial softmax stats.
// L[b][i][j] = sqrt(C) * K[b][i].Q[b][j].  Tile 128 (i) x 128 (j), K=256.
// 4 warps (128 thr), warp tile 64x64, 2 CTAs/SM, 3-stage pipeline.
// Each warp-slab (64 i-rows) reduces per-column (max, sum) into g_pm/g_ps.
// ---------------------------------------------------------------------------
#define LG_STG 32768     // A0 8K | A1 8K | B0 8K | B1 8K
#define LG_SMEM (3 * LG_STG)

__global__ void __launch_bounds__(128, 2) logits_h_kernel()
{
    const int bx = blockIdx.x, by = blockIdx.y, b = blockIdx.z;
    if (bx < by) return;                      // all i < j: fully masked, never read
    const int i0 = bx * 128;
    const int j0 = by * 128;
    const size_t rowb = (size_t)b * NT;

    extern __shared__ char sm[];
    const uint32_t smb = smem_u32(sm);
    const int tid = threadIdx.x;
    const int wid = tid >> 5, lane = tid & 31;
    const int wr = wid >> 1, wc = wid & 1;
    const int wm = wr * 64, wn = wc * 64;

    float acc[4][8][4] = {};

    auto issue = [&](int c, int buf) {
        const uint32_t base = smb + buf * LG_STG;
#pragma unroll
        for (int it = 0; it < 8; it++) {
            int idx = tid + it * 128;      // 1024: 2 terms x 128 rows x 4
            int t = idx >> 9, rem = idx & 511;
            int r = rem >> 2, u = rem & 3;
            cp_async16(base + t * 8192 + sw64((uint32_t)(r * 64 + u * 16)),
                       g_Kh[t] + (rowb + i0 + r) * NH + (size_t)c * 32 + u * 8);
        }
#pragma unroll
        for (int it = 0; it < 8; it++) {
            int idx = tid + it * 128;
            int t = idx >> 9, rem = idx & 511;
            int n = rem >> 2, u = rem & 3;
            cp_async16(base + 16384 + t * 8192 + sw64((uint32_t)(n * 64 + u * 16)),
                       g_Qh[t] + (rowb + j0 + n) * NH + (size_t)c * 32 + u * 8);
        }
        CP_COMMIT();
    };

    const int KT = NH / 32;   // 8
    issue(0, 0);
    issue(1, 1);
    for (int c = 0; c < KT; c++) {
        const int cur = c % 3;
        CP_WAIT1();
        __syncthreads();
        if (c + 2 < KT) issue(c + 2, (c + 2) % 3);
        const uint32_t base = smb + cur * LG_STG;
        mma_terms<4>(base, base + 8192, base + 16384, base + 24576,
                     3, wm, wn, lane, acc);
    }

    const float scale = 45.25483399593904f;  // sqrt(2048)
    float* Lb = g_L + (size_t)b * NT * NT;
#pragma unroll
    for (int mi = 0; mi < 4; mi++) {
        int m = wm + mi * 16 + (lane >> 2);
#pragma unroll
        for (int jj = 0; jj < 8; jj++) {
            int n = wn + jj * 8 + (lane & 3) * 2;
            int jg = j0 + n;
            {
                int ig = i0 + m;
                float2 v;
                v.x = (ig >= jg) ? acc[mi][jj][0] * scale : -INFINITY;
                v.y = (ig >= jg + 1) ? acc[mi][jj][1] * scale : -INFINITY;
                *(float2*)(Lb + (size_t)ig * NT + jg) = v;
            }
            {
                int ig = i0 + m + 8;
                float2 v;
                v.x = (ig >= jg) ? acc[mi][jj][2] * scale : -INFINITY;
                v.y = (ig >= jg + 1) ? acc[mi][jj][3] * scale : -INFINITY;
                *(float2*)(Lb + (size_t)ig * NT + jg) = v;
            }
        }
    }

    // ---- partial softmax stats: per-column (max, sum) over this warp's 64 rows
    {
        const int bi2 = bx * 2 + wr;
        float* pmrow = g_pm + ((size_t)b * 32 + bi2) * NT;
        float* psrow = g_ps + ((size_t)b * 32 + bi2) * NT;
#pragma unroll
        for (int jj = 0; jj < 8; jj++) {
#pragma unroll
            for (int q = 0; q < 2; q++) {
                int jg = j0 + wn + jj * 8 + (lane & 3) * 2 + q;
                float v[8];
#pragma unroll
                for (int mi = 0; mi < 4; mi++) {
                    int ig = i0 + wm + mi * 16 + (lane >> 2);
                    v[2 * mi]     = (ig >= jg)     ? acc[mi][jj][q] * scale     : -INFINITY;
                    v[2 * mi + 1] = (ig + 8 >= jg) ? acc[mi][jj][q + 2] * scale : -INFINITY;
                }
                float mc = v[0];
#pragma unroll
                for (int k = 1; k < 8; k++) mc = fmaxf(mc, v[k]);
#pragma unroll
                for (int o = 4; o <= 16; o <<= 1)
                    mc = fmaxf(mc, __shfl_xor_sync(0xffffffffu, mc, o));
                float s = 0.f;
#pragma unroll
                for (int k = 0; k < 8; k++)
                    if (v[k] != -INFINITY) s += __expf(v[k] - mc);
#pragma unroll
                for (int o = 4; o <= 16; o <<= 1)
                    s += __shfl_xor_sync(0xffffffffu, s, o);
                if ((lane >> 2) == 0) { pmrow[jg] = mc; psrow[jg] = s; }
            }
        }
    }
}

// ---------------------------------------------------------------------------
// Kernel 3: combine partial stats -> g_m, g_rs.
// Valid slabs for column j: bi2 >= 2*(j>>7) (exactly the blocks that ran).
// ---------------------------------------------------------------------------
__global__ void __launch_bounds__(128) combine_kernel()
{
    const int j = blockIdx.x * 128 + threadIdx.x;
    const int b = blockIdx.y;
    const int k0 = (j >> 7) * 2;
    const float* pm = g_pm + (size_t)b * 32 * NT;
    const float* ps = g_ps + (size_t)b * 32 * NT;
    float m = -INFINITY;
    for (int k = k0; k < 32; k++) m = fmaxf(m, pm[(size_t)k * NT + j]);
    float s = 0.f;
    for (int k = k0; k < 32; k++) {
        float p = pm[(size_t)k * NT + j];
        if (p != -INFINITY) s += ps[(size_t)k * NT + j] * __expf(p - m);
    }
    g_m[b * NT + j] = m;
    g_rs[b * NT + j] = 1.0f / s;
}

// ---------------------------------------------------------------------------
// Kernel 4: av (fp16 MMA).  out[b][i][h] = sum_{j<=i} P[i][j] * V[j][h]
// Tile M=64 (i) x N=256 (h), 2 CTAs/SM, warp tile 32x64, exp fused in loader.
// ---------------------------------------------------------------------------
#define AV_STG 20480     // A 4K | B 16K
#define AV_SMEM (2 * AV_STG)

__global__ void __launch_bounds__(256, 2) av_h_kernel(float* __restrict__ Out)
{
    extern __shared__ char sm[];
    const uint32_t smb = smem_u32(sm);
    const int tid = threadIdx.x;
    const int wid = tid >> 5, lane = tid & 31;
    const int wm = (wid >> 2) * 32, wn = (wid & 3) * 64;
    const int b = blockIdx.y;
    const int i0 = (gridDim.x - 1 - blockIdx.x) * 64;   // big tiles first
    const float* Lb = g_L + (size_t)b * NT * NT;
    const float* mb = g_m + b * NT;
    const float* rb = g_rs + b * NT;
    const __half* Vt = g_Vth + (size_t)b * NH * NT;
    const int ar = tid >> 3, au = tid & 7;

    float acc[2][8][4] = {};

    auto load_p = [&](int c, float4* lv, float4& m4, float4& r4) {
        m4 = *(const float4*)(mb + c * 32 + au * 4);
        r4 = *(const float4*)(rb + c * 32 + au * 4);
#pragma unroll
        for (int it = 0; it < 2; it++)
            lv[it] = *(const float4*)(Lb + (size_t)(i0 + ar + it * 32) * NT +
                                      (size_t)c * 32 + au * 4);
    };
    auto store_p = [&](int buf, const float4* lv, const float4& m4, const float4& r4) {
#pragma unroll
        for (int it = 0; it < 2; it++) {
            __half px = __float2half_rn(__expf(lv[it].x - m4.x) * r4.x);
            __half py = __float2half_rn(__expf(lv[it].y - m4.y) * r4.y);
            __half pz = __float2half_rn(__expf(lv[it].z - m4.z) * r4.z);
            __half pw = __float2half_rn(__expf(lv[it].w - m4.w) * r4.w);
            uint32_t off = sw64((uint32_t)((ar + it * 32) * 64 + au * 8));
            *(uint2*)(sm + buf * AV_STG + off) =
                make_uint2((uint32_t)__half_as_ushort(px) | ((uint32_t)__half_as_ushort(py) << 16),
                           (uint32_t)__half_as_ushort(pz) | ((uint32_t)__half_as_ushort(pw) << 16));
        }
    };
    auto issue_v = [&](int c, int buf) {
#pragma unroll
        for (int it = 0; it < 4; it++) {
            int idx = tid + it * 256;      // 1024 granules: 256 rows x 4
            int n = idx >> 2, u = idx & 3;
            cp_async16(smb + buf * AV_STG + 4096 + sw64((uint32_t)(n * 64 + u * 16)),
                       Vt + (size_t)n * NT + (size_t)c * 32 + u * 8);
        }
        CP_COMMIT();
    };

    const int KT = (i0 + 64) / 32;

    {
        float4 lv[2], m4, r4;
        load_p(0, lv, m4, r4);
        issue_v(0, 0);
        store_p(0, lv, m4, r4);
        CP_WAIT0();
        __syncthreads();
    }

    for (int c = 0; c < KT; c++) {
        const int cur = c & 1;
        float4 lv[2], m4, r4;
        if (c + 1 < KT) {
            issue_v(c + 1, cur ^ 1);
            load_p(c + 1, lv, m4, r4);
        }
        mma_terms<2>(smb + cur * AV_STG, smb + cur * AV_STG,
                     smb + cur * AV_STG + 4096, smb + cur * AV_STG + 4096,
                     1, wm, wn, lane, acc);
        if (c + 1 < KT) {
            store_p(cur ^ 1, lv, m4, r4);
            CP_WAIT0();
        }
        __syncthreads();
    }

    float* Ob = Out + (size_t)b * NT * NH;
#pragma unroll
    for (int mi = 0; mi < 2; mi++) {
        int m = i0 + wm + mi * 16 + (lane >> 2);
#pragma unroll
        for (int jj = 0; jj < 8; jj++) {
            int n = wn + jj * 8 + (lane & 3) * 2;
            *(float2*)(Ob + (size_t)m * NH + n) = make_float2(acc[mi][jj][0], acc[mi][jj][1]);
            *(float2*)(Ob + (size_t)(m + 8) * NH + n) = make_float2(acc[mi][jj][2], acc[mi][jj][3]);
        }
    }
}

// ---------------------------------------------------------------------------
extern "C" void kernel_launch(void* const* d_in, const int* in_sizes, int n_in,
                              void* d_out, int out_size)
{
    const float* X  = (const float*)d_in[0];   // token_embd [16,2048,2048]
    const float* Wk = (const float*)d_in[1];   // [2048,256]
    const float* Wq = (const float*)d_in[2];
    const float* Wv = (const float*)d_in[3];
    float* out = (float*)d_out;                // [16,2048,256] fp32

    cudaFuncSetAttribute(proj_h_kernel,
                         cudaFuncAttributeMaxDynamicSharedMemorySize, PJ_SMEM);
    cudaFuncSetAttribute(logits_h_kernel,
                         cudaFuncAttributeMaxDynamicSharedMemorySize, LG_SMEM);
    cudaFuncSetAttribute(av_h_kernel,
                         cudaFuncAttributeMaxDynamicSharedMemorySize, AV_SMEM);

    xsplit_kernel<<<8192, 256>>>(X);
    wprep_kernel<<<dim3(NC / 32, NH / 32, 3), dim3(32, 8)>>>(Wk, Wq, Wv);

    // x = which*2 + ntile (fastest) -> 6 consecutive blocks share one X tile in L2
    proj_h_kernel<<<dim3(6, BTOT / 128), 128, PJ_SMEM>>>();

    vtrans_kernel<<<dim3(NT / 32, NH / 32, NB), dim3(32, 8)>>>();

    logits_h_kernel<<<dim3(NT / 128, NT / 128, NB), 128, LG_SMEM>>>();

    combine_kernel<<<dim3(NT / 128, NB), 128>>>();

    av_h_kernel<<<dim3(NT / 64, NB), 256, AV_SMEM>>>(out);
}